// round 7
// baseline (speedup 1.0000x reference)
#include <cuda_runtime.h>
#include <cuda_bf16.h>

#define N_NODES 100000
#define E_MAX   3200000
#define NPAD    102400          // padded node count (multiple of 1024)
#define NBLK    98              // NPAD/1024 blocks cover >= N_NODES

// ---------------- device scratch (no allocations allowed) ----------------
__device__ int   g_is64;
__device__ int   g_deg[NPAD];
__device__ int   g_cursor[NPAD];
__device__ int   g_bsum[128];
__device__ int   g_boff[128];
__device__ int   g_rowptr[NPAD + 1];
__device__ float g_invdeg[NPAD];
__device__ int   g_csr[E_MAX];
__device__ float g_agg[(size_t)N_NODES * 128];
__device__ float g_h1 [(size_t)N_NODES * 128];
__device__ float g_h2 [(size_t)N_NODES * 128];
__device__ __nv_bfloat16 g_xb[(size_t)N_NODES * 128];   // bf16 gather source
__device__ float g_G  [(size_t)N_NODES * 8];
__device__ float g_R  [(size_t)N_NODES * 8];

// ---------------- f32x2 packed-FMA helpers (sm_103a) ----------------
__device__ __forceinline__ unsigned long long pk2(float a, float b) {
    unsigned long long r;
    asm("mov.b64 %0, {%1, %2};" : "=l"(r) : "f"(a), "f"(b));
    return r;
}
__device__ __forceinline__ float2 upk2(unsigned long long v) {
    float2 r;
    asm("mov.b64 {%0, %1}, %2;" : "=f"(r.x), "=f"(r.y) : "l"(v));
    return r;
}
__device__ __forceinline__ void fma2(unsigned long long& d,
                                     unsigned long long a,
                                     unsigned long long b) {
    asm("fma.rn.f32x2 %0, %1, %2, %0;" : "+l"(d) : "l"(a), "l"(b));
}

// bf16x2 word -> two f32 via integer shifts (exact): lo<<16, hi&0xffff0000
__device__ __forceinline__ void bf2f(unsigned p, float& f0, float& f1) {
    unsigned u0 = p << 16;
    unsigned u1 = p & 0xffff0000u;
    f0 = __uint_as_float(u0);
    f1 = __uint_as_float(u1);
}

// ---------------- edge-index dtype detection (int32 vs int64) ----------------
__global__ void k_detect(const int* __restrict__ ei) {
    if (threadIdx.x == 0 && blockIdx.x == 0) {
        int acc = 0;
        for (int i = 0; i < 128; i++) acc |= ei[2 * i + 1];
        g_is64 = (acc == 0) ? 1 : 0;
    }
}

__device__ __forceinline__ int load_edge(const void* ei, int is64, size_t idx) {
    return is64 ? (int)((const long long*)ei)[idx] : ((const int*)ei)[idx];
}

// ---------------- CSR build ----------------
__global__ void k_zero() {
    int i = blockIdx.x * blockDim.x + threadIdx.x;
    if (i < NPAD) g_deg[i] = 0;
}

__global__ void k_hist(const void* __restrict__ ei, int E) {
    int is64 = g_is64;
    int stride = gridDim.x * blockDim.x;
    for (int i = blockIdx.x * blockDim.x + threadIdx.x; i < E; i += stride) {
        int d = load_edge(ei, is64, (size_t)E + i);
        atomicAdd(&g_deg[d], 1);
    }
}

__global__ void k_reduce() {
    __shared__ int ws[8];
    int t = threadIdx.x, lane = t & 31, warp = t >> 5;
    int4 v = ((const int4*)g_deg)[blockIdx.x * 256 + t];
    int s = v.x + v.y + v.z + v.w;
    #pragma unroll
    for (int off = 16; off; off >>= 1)
        s += __shfl_xor_sync(0xffffffffu, s, off);
    if (lane == 0) ws[warp] = s;
    __syncthreads();
    if (t == 0) {
        int tot = 0;
        #pragma unroll
        for (int i = 0; i < 8; i++) tot += ws[i];
        g_bsum[blockIdx.x] = tot;
    }
}

// parallel scan of the NBLK block sums (one 128-thread block)
__global__ void k_scanb(int E) {
    __shared__ int ws[4];
    int t = threadIdx.x;            // 0..127
    int lane = t & 31, warp = t >> 5;
    int v = (t < NBLK) ? g_bsum[t] : 0;
    int x = v;
    #pragma unroll
    for (int off = 1; off < 32; off <<= 1) {
        int y = __shfl_up_sync(0xffffffffu, x, off);
        if (lane >= off) x += y;
    }
    if (lane == 31) ws[warp] = x;
    __syncthreads();
    if (t == 0) {
        int r = 0;
        #pragma unroll
        for (int i = 0; i < 4; i++) { int tmp = ws[i]; ws[i] = r; r += tmp; }
    }
    __syncthreads();
    int excl = x - v + ws[warp];
    if (t < NBLK) g_boff[t] = excl;
    if (t == 0) g_rowptr[N_NODES] = E;
}

__global__ void k_scanw() {
    __shared__ int ws[8];
    int blk = blockIdx.x, t = threadIdx.x;
    int lane = t & 31, warp = t >> 5;
    int4 v = ((const int4*)g_deg)[blk * 256 + t];
    int tsum = v.x + v.y + v.z + v.w;
    int x = tsum;
    #pragma unroll
    for (int off = 1; off < 32; off <<= 1) {
        int y = __shfl_up_sync(0xffffffffu, x, off);
        if (lane >= off) x += y;
    }
    if (lane == 31) ws[warp] = x;
    __syncthreads();
    if (warp == 0) {
        int w = (lane < 8) ? ws[lane] : 0;
        #pragma unroll
        for (int off = 1; off < 8; off <<= 1) {
            int y = __shfl_up_sync(0xffffffffu, w, off);
            if (lane >= off) w += y;
        }
        if (lane < 8) ws[lane] = w;
    }
    __syncthreads();
    int excl = x - tsum + (warp ? ws[warp - 1] : 0) + g_boff[blk];
    int base = blk * 1024 + t * 4;
    int run = excl;
    g_rowptr[base + 0] = run; g_cursor[base + 0] = run;
    g_invdeg[base + 0] = 1.0f / (float)(v.x > 1 ? v.x : 1);
    run += v.x;
    g_rowptr[base + 1] = run; g_cursor[base + 1] = run;
    g_invdeg[base + 1] = 1.0f / (float)(v.y > 1 ? v.y : 1);
    run += v.y;
    g_rowptr[base + 2] = run; g_cursor[base + 2] = run;
    g_invdeg[base + 2] = 1.0f / (float)(v.z > 1 ? v.z : 1);
    run += v.z;
    g_rowptr[base + 3] = run; g_cursor[base + 3] = run;
    g_invdeg[base + 3] = 1.0f / (float)(v.w > 1 ? v.w : 1);
    run += v.w;
}

__global__ void k_scatter(const void* __restrict__ ei, int E) {
    int is64 = g_is64;
    int stride = gridDim.x * blockDim.x;
    for (int i = blockIdx.x * blockDim.x + threadIdx.x; i < E; i += stride) {
        int s = load_edge(ei, is64, i);
        int d = load_edge(ei, is64, (size_t)E + i);
        int pos = atomicAdd(&g_cursor[d], 1);
        g_csr[pos] = s;
    }
}

// ---------------- fp32 -> bf16 feature conversion ----------------
__global__ void k_cvt(const float* __restrict__ in) {
    size_t i = (size_t)blockIdx.x * 256 + threadIdx.x;   // float4 index
    float4 v = ((const float4*)in)[i];
    __nv_bfloat162 a = __floats2bfloat162_rn(v.x, v.y);
    __nv_bfloat162 b = __floats2bfloat162_rn(v.z, v.w);
    uint2 u;
    u.x = *(unsigned*)&a;
    u.y = *(unsigned*)&b;
    ((uint2*)g_xb)[i] = u;
}

// ---------------- mean aggregation from bf16 rows (warp per node, MLP 4) ------
// row = 128 bf16 = 256 bytes = 32 uint2; each of 32 lanes loads one uint2.
__global__ void k_agg_bf(float* __restrict__ o) {
    int gw = (blockIdx.x * blockDim.x + threadIdx.x) >> 5;   // node id
    int lane = threadIdx.x & 31;
    int beg = g_rowptr[gw], end = g_rowptr[gw + 1];
    const uint2* __restrict__ hb = (const uint2*)g_xb;       // 32 uint2 per row
    const int*  __restrict__ csr = g_csr;

    float a0 = 0.f, a1 = 0.f, a2 = 0.f, a3 = 0.f;
    int e = beg;
    for (; e + 4 <= end; e += 4) {
        int s0 = __ldg(csr + e);
        int s1 = __ldg(csr + e + 1);
        int s2 = __ldg(csr + e + 2);
        int s3 = __ldg(csr + e + 3);
        uint2 p0 = __ldg(hb + (size_t)s0 * 32 + lane);
        uint2 p1 = __ldg(hb + (size_t)s1 * 32 + lane);
        uint2 p2 = __ldg(hb + (size_t)s2 * 32 + lane);
        uint2 p3 = __ldg(hb + (size_t)s3 * 32 + lane);
        float f0, f1, f2, f3;
        bf2f(p0.x, f0, f1); bf2f(p0.y, f2, f3);
        a0 += f0; a1 += f1; a2 += f2; a3 += f3;
        bf2f(p1.x, f0, f1); bf2f(p1.y, f2, f3);
        a0 += f0; a1 += f1; a2 += f2; a3 += f3;
        bf2f(p2.x, f0, f1); bf2f(p2.y, f2, f3);
        a0 += f0; a1 += f1; a2 += f2; a3 += f3;
        bf2f(p3.x, f0, f1); bf2f(p3.y, f2, f3);
        a0 += f0; a1 += f1; a2 += f2; a3 += f3;
    }
    for (; e < end; e++) {
        int s0 = __ldg(csr + e);
        uint2 p0 = __ldg(hb + (size_t)s0 * 32 + lane);
        float f0, f1, f2, f3;
        bf2f(p0.x, f0, f1); bf2f(p0.y, f2, f3);
        a0 += f0; a1 += f1; a2 += f2; a3 += f3;
    }
    float d = g_invdeg[gw];
    float4 r;
    r.x = a0 * d; r.y = a1 * d; r.z = a2 * d; r.w = a3 * d;
    ((float4*)(o + (size_t)gw * 128))[lane] = r;
}

// NOTE on layout: lane reads bf16 elements [lane*4, lane*4+4) of the row, and
// the f32 accumulators map to output floats [lane*4, lane*4+4) — matches the
// float4 store below (same mapping as rounds 3/4).

// ---------------- fused GEMM: out = relu(agg@Wl^T + h@Wr^T + b) ----------------
// C[N,128] = A[N,256] * B[256,128],  A = [agg | h],  B[k][j] = Wl/Wr[j][k]
// BM=64, BN=128, BK=16, 256 threads, thread tile 8 rows x 4 cols, f32x2 FMAs.
// WB: also emit bf16 copy of the output into g_xb (gather source for next layer).
template <int RELU, int WB>
__global__ __launch_bounds__(256, 2)
void k_gemm(const float* __restrict__ Ag, const float* __restrict__ Hm,
            const float* __restrict__ Wl, const float* __restrict__ Wr,
            const float* __restrict__ bias, float* __restrict__ out)
{
    __shared__ __align__(16) float As[2][16][66];
    __shared__ __align__(16) float Bs[2][16][132];

    const int tid  = threadIdx.x;
    const int bm0  = blockIdx.x * 64;
    const int warp = tid >> 5, lane = tid & 31;
    const int row0 = (warp & 1) * 32 + (lane & 3) * 8;     // 0..56, step 8
    const int col0 = (warp >> 1) * 32 + (lane >> 2) * 4;   // 0..124, step 4
    const int arow = tid >> 2, akq = tid & 3;
    const int grow = bm0 + arow;
    const bool rok = grow < N_NODES;
    const int bj0 = tid >> 2, bkq = tid & 3;

    float4 ar, br0, br1;

#define GLOAD(kt) {                                                              \
    int gk = (kt) * 16 + akq * 4;                                                \
    if (rok) {                                                                   \
        const float* p = (gk < 128) ? (Ag + (size_t)grow * 128 + gk)             \
                                    : (Hm + (size_t)grow * 128 + (gk - 128));    \
        ar = *(const float4*)p;                                                  \
    } else ar = make_float4(0.f, 0.f, 0.f, 0.f);                                 \
    int gkb = (kt) * 16 + bkq * 4;                                               \
    { const float* p = (gkb < 128) ? (Wl + bj0 * 128 + gkb)                      \
                                   : (Wr + bj0 * 128 + (gkb - 128));             \
      br0 = *(const float4*)p; }                                                 \
    { int bj1 = bj0 + 64;                                                        \
      const float* p = (gkb < 128) ? (Wl + bj1 * 128 + gkb)                      \
                                   : (Wr + bj1 * 128 + (gkb - 128));             \
      br1 = *(const float4*)p; }                                                 \
}
#define SSTORE(s) {                                                              \
    As[s][akq * 4 + 0][arow] = ar.x; As[s][akq * 4 + 1][arow] = ar.y;            \
    As[s][akq * 4 + 2][arow] = ar.z; As[s][akq * 4 + 3][arow] = ar.w;            \
    Bs[s][bkq * 4 + 0][bj0] = br0.x; Bs[s][bkq * 4 + 1][bj0] = br0.y;            \
    Bs[s][bkq * 4 + 2][bj0] = br0.z; Bs[s][bkq * 4 + 3][bj0] = br0.w;            \
    Bs[s][bkq * 4 + 0][bj0 + 64] = br1.x; Bs[s][bkq * 4 + 1][bj0 + 64] = br1.y;  \
    Bs[s][bkq * 4 + 2][bj0 + 64] = br1.z; Bs[s][bkq * 4 + 3][bj0 + 64] = br1.w;  \
}

    unsigned long long acc[4][4];
    #pragma unroll
    for (int p = 0; p < 4; p++)
        #pragma unroll
        for (int j = 0; j < 4; j++) acc[p][j] = 0ull;

    GLOAD(0);
    SSTORE(0);
    __syncthreads();

    #pragma unroll 1
    for (int kt = 0; kt < 16; kt++) {
        int s = kt & 1;
        if (kt < 15) GLOAD(kt + 1);
        #pragma unroll
        for (int kk = 0; kk < 16; kk++) {
            unsigned long long a2[4];
            #pragma unroll
            for (int p = 0; p < 4; p++)
                a2[p] = *(const unsigned long long*)&As[s][kk][row0 + 2 * p];
            float4 b4 = *(const float4*)&Bs[s][kk][col0];
            unsigned long long bb0 = pk2(b4.x, b4.x);
            unsigned long long bb1 = pk2(b4.y, b4.y);
            unsigned long long bb2 = pk2(b4.z, b4.z);
            unsigned long long bb3 = pk2(b4.w, b4.w);
            #pragma unroll
            for (int p = 0; p < 4; p++) {
                fma2(acc[p][0], a2[p], bb0);
                fma2(acc[p][1], a2[p], bb1);
                fma2(acc[p][2], a2[p], bb2);
                fma2(acc[p][3], a2[p], bb3);
            }
        }
        if (kt < 15) { SSTORE(s ^ 1); __syncthreads(); }
    }

    float4 b4 = *(const float4*)&bias[col0];
    #pragma unroll
    for (int p = 0; p < 4; p++) {
        float2 c0 = upk2(acc[p][0]), c1 = upk2(acc[p][1]);
        float2 c2 = upk2(acc[p][2]), c3 = upk2(acc[p][3]);
        float4 lo = make_float4(c0.x + b4.x, c1.x + b4.y, c2.x + b4.z, c3.x + b4.w);
        float4 hi = make_float4(c0.y + b4.x, c1.y + b4.y, c2.y + b4.z, c3.y + b4.w);
        if (RELU) {
            lo.x = fmaxf(lo.x, 0.f); lo.y = fmaxf(lo.y, 0.f);
            lo.z = fmaxf(lo.z, 0.f); lo.w = fmaxf(lo.w, 0.f);
            hi.x = fmaxf(hi.x, 0.f); hi.y = fmaxf(hi.y, 0.f);
            hi.z = fmaxf(hi.z, 0.f); hi.w = fmaxf(hi.w, 0.f);
        }
        int r0 = bm0 + row0 + 2 * p;
        if (r0 < N_NODES) {
            *(float4*)&out[(size_t)r0 * 128 + col0] = lo;
            if (WB) {
                __nv_bfloat162 q0 = __floats2bfloat162_rn(lo.x, lo.y);
                __nv_bfloat162 q1 = __floats2bfloat162_rn(lo.z, lo.w);
                uint2 u; u.x = *(unsigned*)&q0; u.y = *(unsigned*)&q1;
                *(uint2*)&g_xb[(size_t)r0 * 128 + col0] = u;
            }
        }
        if (r0 + 1 < N_NODES) {
            *(float4*)&out[(size_t)(r0 + 1) * 128 + col0] = hi;
            if (WB) {
                __nv_bfloat162 q0 = __floats2bfloat162_rn(hi.x, hi.y);
                __nv_bfloat162 q1 = __floats2bfloat162_rn(hi.z, hi.w);
                uint2 u; u.x = *(unsigned*)&q0; u.y = *(unsigned*)&q1;
                *(uint2*)&g_xb[(size_t)(r0 + 1) * 128 + col0] = u;
            }
        }
    }
#undef GLOAD
#undef SSTORE
}

// ---------------- layer-3 thin projections: G = H2@Wl3^T, R = H2@Wr3^T + b3 ----
__global__ void k_gemm3(const float* __restrict__ H,
                        const float* __restrict__ Wl, const float* __restrict__ Wr,
                        const float* __restrict__ b) {
    __shared__ __align__(16) float sW[12 * 128];
    __shared__ float sb[8];
    int t = threadIdx.x;
    for (int i = t; i < 1536; i += 256) sW[i] = (i < 768) ? Wl[i] : Wr[i - 768];
    if (t < 6) sb[t] = b[t];
    __syncthreads();
    int lane = t & 31, warp = t >> 5;
    int node = blockIdx.x * 8 + warp;
    float4 h4 = ((const float4*)(H + (size_t)node * 128))[lane];
    float r[12];
    #pragma unroll
    for (int j = 0; j < 12; j++) {
        float4 w = ((const float4*)(sW + j * 128))[lane];
        r[j] = h4.x * w.x + h4.y * w.y + h4.z * w.z + h4.w * w.w;
    }
    #pragma unroll
    for (int j = 0; j < 12; j++) {
        #pragma unroll
        for (int off = 16; off; off >>= 1)
            r[j] += __shfl_xor_sync(0xffffffffu, r[j], off);
    }
    if (lane == 0) {
        #pragma unroll
        for (int j = 0; j < 6; j++) {
            g_G[(size_t)node * 8 + j] = r[j];
            g_R[(size_t)node * 8 + j] = r[j + 6] + sb[j];
        }
    }
}

// ---------------- final: out = invdeg * sum_e G[src] + R  (6-dim aggregation) ----
__global__ void k_final(float* __restrict__ out) {
    int gw = (blockIdx.x * blockDim.x + threadIdx.x) >> 5;   // node
    int lane = threadIdx.x & 31;
    int sub = lane >> 3, c = lane & 7;                       // 4 neighbors x 8 lanes
    int beg = g_rowptr[gw], end = g_rowptr[gw + 1];
    float acc = 0.f;
    for (int e = beg + sub; e < end; e += 4) {
        int s = g_csr[e];
        acc += g_G[(size_t)s * 8 + c];
    }
    acc += __shfl_xor_sync(0xffffffffu, acc, 8);
    acc += __shfl_xor_sync(0xffffffffu, acc, 16);
    if (lane < 6)
        out[(size_t)gw * 6 + lane] = acc * g_invdeg[gw] + g_R[(size_t)gw * 8 + lane];
}

// ---------------- host launcher ----------------
extern "C" void kernel_launch(void* const* d_in, const int* in_sizes, int n_in,
                              void* d_out, int out_size) {
    const float* x   = (const float*)d_in[0];
    const void*  ei  = d_in[1];
    const float *Wl1 = (const float*)d_in[2], *Wr1 = (const float*)d_in[3], *b1 = (const float*)d_in[4];
    const float *Wl2 = (const float*)d_in[5], *Wr2 = (const float*)d_in[6], *b2 = (const float*)d_in[7];
    const float *Wl3 = (const float*)d_in[8], *Wr3 = (const float*)d_in[9], *b3 = (const float*)d_in[10];
    float* out = (float*)d_out;
    int E = in_sizes[1] / 2;

    float *agg, *h1, *h2;
    cudaGetSymbolAddress((void**)&agg, g_agg);
    cudaGetSymbolAddress((void**)&h1,  g_h1);
    cudaGetSymbolAddress((void**)&h2,  g_h2);

    // CSR build (counting sort by destination)
    k_detect<<<1, 32>>>((const int*)ei);
    k_zero<<<NPAD / 256, 256>>>();
    k_hist<<<2560, 256>>>(ei, E);
    k_reduce<<<NBLK, 256>>>();
    k_scanb<<<1, 128>>>(E);
    k_scanw<<<NBLK, 256>>>();
    k_scatter<<<2560, 256>>>(ei, E);
    k_cvt<<<(N_NODES * 128 / 4) / 256, 256>>>(x);   // x -> bf16

    // layer 1 (gemm epilogue emits bf16 h1 into g_xb)
    k_agg_bf<<<N_NODES / 8, 256>>>(agg);
    k_gemm<1, 1><<<(N_NODES + 63) / 64, 256>>>(agg, x, Wl1, Wr1, b1, h1);
    // layer 2
    k_agg_bf<<<N_NODES / 8, 256>>>(agg);
    k_gemm<1, 0><<<(N_NODES + 63) / 64, 256>>>(agg, h1, Wl2, Wr2, b2, h2);
    // layer 3 (project to 6 dims first, then aggregate cheap)
    k_gemm3<<<N_NODES / 8, 256>>>(h2, Wl3, Wr3, b3);
    k_final<<<N_NODES / 8, 256>>>(out);
}

// round 9
// speedup vs baseline: 1.2036x; 1.2036x over previous
#include <cuda_runtime.h>
#include <cuda_bf16.h>
#include <cstdint>

#define N_NODES 100000
#define E_MAX   3200000
#define NPAD    102400
#define NBLK    98
#define NT      782                     // ceil(N_NODES/128) tiles

// ---------------- device scratch ----------------
__device__ int   g_is64;
__device__ int   g_deg[NPAD];
__device__ int   g_cursor[NPAD];
__device__ int   g_bsum[128];
__device__ int   g_boff[128];
__device__ int   g_rowptr[NPAD + 1];
__device__ float g_invdeg[NPAD];
__device__ int   g_csr[E_MAX];
__device__ __nv_bfloat16 g_xb[(size_t)N_NODES * 128];   // bf16 gather source
__device__ float g_A [(size_t)NT * 128 * 256];          // [agg | h] tf32-rounded f32
__device__ float g_h2[(size_t)N_NODES * 128];
__device__ float g_pB[2][32 * 16 * 32 * 2];             // per-layer permuted B (float2)
__device__ float g_G [(size_t)N_NODES * 8];
__device__ float g_R [(size_t)N_NODES * 8];

// ---------------- helpers ----------------
__device__ __forceinline__ uint32_t pkbf(float a, float b) {
    __nv_bfloat162 v = __floats2bfloat162_rn(a, b);
    return *(uint32_t*)&v;
}
__device__ __forceinline__ float tf32r(float f) {
    uint32_t u;
    asm("cvt.rna.tf32.f32 %0, %1;" : "=r"(u) : "f"(f));
    return __uint_as_float(u);
}
#define MMA_TF32(c, a0, a1, a2, a3, b0, b1)                                        \
    asm volatile("mma.sync.aligned.m16n8k8.row.col.f32.tf32.tf32.f32 "             \
                 "{%0,%1,%2,%3}, {%4,%5,%6,%7}, {%8,%9}, {%0,%1,%2,%3};"           \
                 : "+f"((c)[0]), "+f"((c)[1]), "+f"((c)[2]), "+f"((c)[3])          \
                 : "r"(a0), "r"(a1), "r"(a2), "r"(a3), "r"(b0), "r"(b1))

// ---------------- edge dtype detect ----------------
__global__ void k_detect(const int* __restrict__ ei) {
    if (threadIdx.x == 0 && blockIdx.x == 0) {
        int acc = 0;
        for (int i = 0; i < 128; i++) acc |= ei[2 * i + 1];
        g_is64 = (acc == 0) ? 1 : 0;
    }
}
__device__ __forceinline__ int load_edge(const void* ei, int is64, size_t idx) {
    return is64 ? (int)((const long long*)ei)[idx] : ((const int*)ei)[idx];
}

// ---------------- CSR build ----------------
__global__ void k_zero() {
    int i = blockIdx.x * blockDim.x + threadIdx.x;
    if (i < NPAD) g_deg[i] = 0;
}
__global__ void k_hist(const void* __restrict__ ei, int E) {
    int is64 = g_is64;
    int stride = gridDim.x * blockDim.x;
    for (int i = blockIdx.x * blockDim.x + threadIdx.x; i < E; i += stride)
        atomicAdd(&g_deg[load_edge(ei, is64, (size_t)E + i)], 1);
}
__global__ void k_reduce() {
    __shared__ int ws[8];
    int t = threadIdx.x, lane = t & 31, warp = t >> 5;
    int4 v = ((const int4*)g_deg)[blockIdx.x * 256 + t];
    int s = v.x + v.y + v.z + v.w;
    #pragma unroll
    for (int off = 16; off; off >>= 1) s += __shfl_xor_sync(0xffffffffu, s, off);
    if (lane == 0) ws[warp] = s;
    __syncthreads();
    if (t == 0) {
        int tot = 0;
        #pragma unroll
        for (int i = 0; i < 8; i++) tot += ws[i];
        g_bsum[blockIdx.x] = tot;
    }
}
__global__ void k_scanb(int E) {
    __shared__ int ws[4];
    int t = threadIdx.x, lane = t & 31, warp = t >> 5;
    int v = (t < NBLK) ? g_bsum[t] : 0;
    int x = v;
    #pragma unroll
    for (int off = 1; off < 32; off <<= 1) {
        int y = __shfl_up_sync(0xffffffffu, x, off);
        if (lane >= off) x += y;
    }
    if (lane == 31) ws[warp] = x;
    __syncthreads();
    if (t == 0) {
        int r = 0;
        #pragma unroll
        for (int i = 0; i < 4; i++) { int tmp = ws[i]; ws[i] = r; r += tmp; }
    }
    __syncthreads();
    int excl = x - v + ws[warp];
    if (t < NBLK) g_boff[t] = excl;
    if (t == 0) g_rowptr[N_NODES] = E;
}
__global__ void k_scanw() {
    __shared__ int ws[8];
    int blk = blockIdx.x, t = threadIdx.x;
    int lane = t & 31, warp = t >> 5;
    int4 v = ((const int4*)g_deg)[blk * 256 + t];
    int tsum = v.x + v.y + v.z + v.w;
    int x = tsum;
    #pragma unroll
    for (int off = 1; off < 32; off <<= 1) {
        int y = __shfl_up_sync(0xffffffffu, x, off);
        if (lane >= off) x += y;
    }
    if (lane == 31) ws[warp] = x;
    __syncthreads();
    if (warp == 0) {
        int w = (lane < 8) ? ws[lane] : 0;
        #pragma unroll
        for (int off = 1; off < 8; off <<= 1) {
            int y = __shfl_up_sync(0xffffffffu, w, off);
            if (lane >= off) w += y;
        }
        if (lane < 8) ws[lane] = w;
    }
    __syncthreads();
    int excl = x - tsum + (warp ? ws[warp - 1] : 0) + g_boff[blk];
    int base = blk * 1024 + t * 4;
    int run = excl;
    g_rowptr[base + 0] = run; g_cursor[base + 0] = run;
    g_invdeg[base + 0] = 1.0f / (float)(v.x > 1 ? v.x : 1);
    run += v.x;
    g_rowptr[base + 1] = run; g_cursor[base + 1] = run;
    g_invdeg[base + 1] = 1.0f / (float)(v.y > 1 ? v.y : 1);
    run += v.y;
    g_rowptr[base + 2] = run; g_cursor[base + 2] = run;
    g_invdeg[base + 2] = 1.0f / (float)(v.z > 1 ? v.z : 1);
    run += v.z;
    g_rowptr[base + 3] = run; g_cursor[base + 3] = run;
    g_invdeg[base + 3] = 1.0f / (float)(v.w > 1 ? v.w : 1);
    run += v.w;
}
__global__ void k_scatter(const void* __restrict__ ei, int E) {
    int is64 = g_is64;
    int stride = gridDim.x * blockDim.x;
    for (int i = blockIdx.x * blockDim.x + threadIdx.x; i < E; i += stride) {
        int s = load_edge(ei, is64, i);
        int d = load_edge(ei, is64, (size_t)E + i);
        g_csr[atomicAdd(&g_cursor[d], 1)] = s;
    }
}

// ---------------- weight prep: permuted tf32 B fragments ----------------
// pB[L][(s*16 + j)*32 + t] = float2( B[j*8+t/4][s*8+t%4], B[j*8+t/4][s*8+t%4+4] )
// where B[n][k] = k<128 ? Wl[n][k] : Wr[n][k-128]
__global__ void k_prepw(const float* __restrict__ Wl1, const float* __restrict__ Wr1,
                        const float* __restrict__ Wl2, const float* __restrict__ Wr2) {
    int i = blockIdx.x * blockDim.x + threadIdx.x;     // 2*16384
    int L = i >> 14, rem = i & 16383;
    int s = rem >> 9, j = (rem >> 5) & 15, t = rem & 31;
    const float* Wl = L ? Wl2 : Wl1;
    const float* Wr = L ? Wr2 : Wr1;
    int n = j * 8 + (t >> 2);
    int k0 = s * 8 + (t & 3);
    int k1 = k0 + 4;
    float w0 = (k0 < 128) ? Wl[n * 128 + k0] : Wr[n * 128 + (k0 - 128)];
    float w1 = (k1 < 128) ? Wl[n * 128 + k1] : Wr[n * 128 + (k1 - 128)];
    float2* dst = (float2*)&g_pB[L][0];
    dst[(s * 16 + j) * 32 + t] = make_float2(tf32r(w0), tf32r(w1));
}

// ---------------- x -> bf16 gather source + A cols 128..255 ----------------
__global__ void k_cvt(const float* __restrict__ in) {
    int i = blockIdx.x * blockDim.x + threadIdx.x;     // node*32 + q
    int node = i >> 5, q = i & 31;
    int k0 = q * 4;
    float4 v = *(const float4*)(in + (size_t)node * 128 + k0);
    uint2 u;
    u.x = pkbf(v.x, v.y);
    u.y = pkbf(v.z, v.w);
    *(uint2*)&g_xb[(size_t)node * 128 + k0] = u;
    float4 tv = make_float4(tf32r(v.x), tf32r(v.y), tf32r(v.z), tf32r(v.w));
    *(float4*)(g_A + (size_t)node * 256 + 128 + k0) = tv;
}

// ---------------- mean aggregation -> A cols 0..127 (tf32) ----------------
__global__ void k_agg_bf() {
    int gw = (blockIdx.x * blockDim.x + threadIdx.x) >> 5;
    int lane = threadIdx.x & 31;
    int beg = g_rowptr[gw], end = g_rowptr[gw + 1];
    const uint2* __restrict__ hb = (const uint2*)g_xb;   // 32 uint2 per row
    const int* __restrict__ csr = g_csr;
    float a0 = 0.f, a1 = 0.f, a2 = 0.f, a3 = 0.f;
    int e = beg;
    for (; e + 4 <= end; e += 4) {
        int s0 = __ldg(csr + e), s1 = __ldg(csr + e + 1);
        int s2 = __ldg(csr + e + 2), s3 = __ldg(csr + e + 3);
        uint2 p0 = __ldg(hb + (size_t)s0 * 32 + lane);
        uint2 p1 = __ldg(hb + (size_t)s1 * 32 + lane);
        uint2 p2 = __ldg(hb + (size_t)s2 * 32 + lane);
        uint2 p3 = __ldg(hb + (size_t)s3 * 32 + lane);
        a0 += __uint_as_float(p0.x << 16) + __uint_as_float(p1.x << 16)
            + __uint_as_float(p2.x << 16) + __uint_as_float(p3.x << 16);
        a1 += __uint_as_float(p0.x & 0xffff0000u) + __uint_as_float(p1.x & 0xffff0000u)
            + __uint_as_float(p2.x & 0xffff0000u) + __uint_as_float(p3.x & 0xffff0000u);
        a2 += __uint_as_float(p0.y << 16) + __uint_as_float(p1.y << 16)
            + __uint_as_float(p2.y << 16) + __uint_as_float(p3.y << 16);
        a3 += __uint_as_float(p0.y & 0xffff0000u) + __uint_as_float(p1.y & 0xffff0000u)
            + __uint_as_float(p2.y & 0xffff0000u) + __uint_as_float(p3.y & 0xffff0000u);
    }
    for (; e < end; e++) {
        int s0 = __ldg(csr + e);
        uint2 p0 = __ldg(hb + (size_t)s0 * 32 + lane);
        a0 += __uint_as_float(p0.x << 16);
        a1 += __uint_as_float(p0.x & 0xffff0000u);
        a2 += __uint_as_float(p0.y << 16);
        a3 += __uint_as_float(p0.y & 0xffff0000u);
    }
    float d = g_invdeg[gw];
    float4 r = make_float4(tf32r(a0 * d), tf32r(a1 * d), tf32r(a2 * d), tf32r(a3 * d));
    *(float4*)(g_A + (size_t)gw * 256 + lane * 4) = r;
}

// ---------------- tf32 mma.sync GEMM: C[128,128] = A[128,256] * B^T ----------
// 8 warps: warp w -> rows w*16..w*16+15; 16 n8-tiles; 32 k8-steps.
// B fragments pre-permuted in smem (one LDS.64 each); A fragments from global
// with 4-kstep software pipeline.
template <int LAYER>
__global__ __launch_bounds__(256, 1) void k_gemm_mma(
    const float* __restrict__ pB, const float* __restrict__ bias,
    float* __restrict__ out_f32)
{
    extern __shared__ float2 sB[];     // [32][16][32]
    int tid = threadIdx.x, wid = tid >> 5, lane = tid & 31;

    // fill B (128 KB)
    {
        const uint4* src = (const uint4*)pB;
        uint4* dst = (uint4*)sB;
        #pragma unroll
        for (int i = 0; i < 32; i++)
            dst[tid + 256 * i] = __ldg(src + tid + 256 * i);
    }
    __syncthreads();

    const float* Ap = g_A + ((size_t)(blockIdx.x * 128 + wid * 16 + (lane >> 2))) * 256 + (lane & 3);

    uint32_t a[2][16];
    float c[16][4];
    #pragma unroll
    for (int j = 0; j < 16; j++) {
        c[j][0] = 0.f; c[j][1] = 0.f; c[j][2] = 0.f; c[j][3] = 0.f;
    }

#define LDA(buf, ch) {                                                          \
    _Pragma("unroll")                                                           \
    for (int q = 0; q < 4; q++) {                                               \
        int s_ = (ch) * 4 + q;                                                  \
        a[buf][q * 4 + 0] = __float_as_uint(__ldg(Ap + s_ * 8));                \
        a[buf][q * 4 + 1] = __float_as_uint(__ldg(Ap + s_ * 8 + 2048));         \
        a[buf][q * 4 + 2] = __float_as_uint(__ldg(Ap + s_ * 8 + 4));            \
        a[buf][q * 4 + 3] = __float_as_uint(__ldg(Ap + s_ * 8 + 2052));         \
    }                                                                           \
}

    LDA(0, 0);
    #pragma unroll 1
    for (int ch = 0; ch < 8; ch++) {
        int buf = ch & 1;
        if (ch < 7) LDA(buf ^ 1, ch + 1);
        #pragma unroll
        for (int q = 0; q < 4; q++) {
            int s = ch * 4 + q;
            const float2* bp = &sB[(s * 16) * 32 + lane];
            #pragma unroll
            for (int j = 0; j < 16; j++) {
                float2 b = bp[j * 32];
                MMA_TF32(c[j], a[buf][q * 4 + 0], a[buf][q * 4 + 1],
                         a[buf][q * 4 + 2], a[buf][q * 4 + 3],
                         __float_as_uint(b.x), __float_as_uint(b.y));
            }
        }
    }
#undef LDA

    // epilogue
    int r0 = blockIdx.x * 128 + wid * 16 + (lane >> 2);
    int r1 = r0 + 8;
    int c2 = (lane & 3) * 2;
    #pragma unroll
    for (int j = 0; j < 16; j++) {
        int col = j * 8 + c2;
        float2 bv = *(const float2*)(bias + col);
        float v00 = fmaxf(c[j][0] + bv.x, 0.f);
        float v01 = fmaxf(c[j][1] + bv.y, 0.f);
        float v10 = fmaxf(c[j][2] + bv.x, 0.f);
        float v11 = fmaxf(c[j][3] + bv.y, 0.f);
        if (LAYER == 0) {
            if (r0 < N_NODES) {
                *(uint32_t*)&g_xb[(size_t)r0 * 128 + col] = pkbf(v00, v01);
                *(float2*)(g_A + (size_t)r0 * 256 + 128 + col) = make_float2(tf32r(v00), tf32r(v01));
            }
            if (r1 < N_NODES) {
                *(uint32_t*)&g_xb[(size_t)r1 * 128 + col] = pkbf(v10, v11);
                *(float2*)(g_A + (size_t)r1 * 256 + 128 + col) = make_float2(tf32r(v10), tf32r(v11));
            }
        } else {
            if (r0 < N_NODES) *(float2*)(out_f32 + (size_t)r0 * 128 + col) = make_float2(v00, v01);
            if (r1 < N_NODES) *(float2*)(out_f32 + (size_t)r1 * 128 + col) = make_float2(v10, v11);
        }
    }
}

// ---------------- layer-3 thin projections + final ----------------
__global__ void k_gemm3(const float* __restrict__ H,
                        const float* __restrict__ Wl, const float* __restrict__ Wr,
                        const float* __restrict__ b) {
    __shared__ __align__(16) float sW[12 * 128];
    __shared__ float sb_[8];
    int t = threadIdx.x;
    for (int i = t; i < 1536; i += 256) sW[i] = (i < 768) ? Wl[i] : Wr[i - 768];
    if (t < 6) sb_[t] = b[t];
    __syncthreads();
    int lane = t & 31, warp = t >> 5;
    int node = blockIdx.x * 8 + warp;
    float4 h4 = ((const float4*)(H + (size_t)node * 128))[lane];
    float r[12];
    #pragma unroll
    for (int j = 0; j < 12; j++) {
        float4 w = ((const float4*)(sW + j * 128))[lane];
        r[j] = h4.x * w.x + h4.y * w.y + h4.z * w.z + h4.w * w.w;
    }
    #pragma unroll
    for (int j = 0; j < 12; j++) {
        #pragma unroll
        for (int off = 16; off; off >>= 1)
            r[j] += __shfl_xor_sync(0xffffffffu, r[j], off);
    }
    if (lane == 0) {
        #pragma unroll
        for (int j = 0; j < 6; j++) {
            g_G[(size_t)node * 8 + j] = r[j];
            g_R[(size_t)node * 8 + j] = r[j + 6] + sb_[j];
        }
    }
}
__global__ void k_final(float* __restrict__ out) {
    int gw = (blockIdx.x * blockDim.x + threadIdx.x) >> 5;
    int lane = threadIdx.x & 31;
    int sub = lane >> 3, c = lane & 7;
    int beg = g_rowptr[gw], end = g_rowptr[gw + 1];
    float acc = 0.f;
    for (int e = beg + sub; e < end; e += 4)
        acc += g_G[(size_t)g_csr[e] * 8 + c];
    acc += __shfl_xor_sync(0xffffffffu, acc, 8);
    acc += __shfl_xor_sync(0xffffffffu, acc, 16);
    if (lane < 6)
        out[(size_t)gw * 6 + lane] = acc * g_invdeg[gw] + g_R[(size_t)gw * 8 + lane];
}

// ---------------- host launcher ----------------
#define SMEM_B (32 * 16 * 32 * 8)   // 131072

extern "C" void kernel_launch(void* const* d_in, const int* in_sizes, int n_in,
                              void* d_out, int out_size) {
    const float* x   = (const float*)d_in[0];
    const void*  ei  = d_in[1];
    const float *Wl1 = (const float*)d_in[2], *Wr1 = (const float*)d_in[3], *b1 = (const float*)d_in[4];
    const float *Wl2 = (const float*)d_in[5], *Wr2 = (const float*)d_in[6], *b2 = (const float*)d_in[7];
    const float *Wl3 = (const float*)d_in[8], *Wr3 = (const float*)d_in[9], *b3 = (const float*)d_in[10];
    float* out = (float*)d_out;
    int E = in_sizes[1] / 2;

    float* h2;
    cudaGetSymbolAddress((void**)&h2, g_h2);
    float* pb;
    cudaGetSymbolAddress((void**)&pb, g_pB);

    cudaFuncSetAttribute(k_gemm_mma<0>, cudaFuncAttributeMaxDynamicSharedMemorySize, SMEM_B);
    cudaFuncSetAttribute(k_gemm_mma<1>, cudaFuncAttributeMaxDynamicSharedMemorySize, SMEM_B);

    // CSR build
    k_detect<<<1, 32>>>((const int*)ei);
    k_zero<<<NPAD / 256, 256>>>();
    k_hist<<<2560, 256>>>(ei, E);
    k_reduce<<<NBLK, 256>>>();
    k_scanb<<<1, 128>>>(E);
    k_scanw<<<NBLK, 256>>>();
    k_scatter<<<2560, 256>>>(ei, E);

    // prep
    k_prepw<<<128, 256>>>(Wl1, Wr1, Wl2, Wr2);
    k_cvt<<<(N_NODES * 32) / 256, 256>>>(x);

    // layer 1 (epilogue writes bf16 gather source + A cols 128..255)
    k_agg_bf<<<N_NODES / 8, 256>>>();
    k_gemm_mma<0><<<NT, 256, SMEM_B>>>(pb, b1, nullptr);
    // layer 2
    k_agg_bf<<<N_NODES / 8, 256>>>();
    k_gemm_mma<1><<<NT, 256, SMEM_B>>>(pb + 32 * 16 * 32 * 2, b2, h2);
    // layer 3
    k_gemm3<<<N_NODES / 8, 256>>>(h2, Wl3, Wr3, b3);
    k_final<<<N_NODES / 8, 256>>>(out);
}